// round 8
// baseline (speedup 1.0000x reference)
#include <cuda_runtime.h>
#include <cuda_pipeline.h>

// ---------------- problem dims (fixed by the dataset) ----------------
#define BATCH   2
#define C_IN    256
#define HH      40
#define WW      40
#define CMID    64     // compressed channels
#define CK      100    // k2 * S^2 encoder output channels
#define KK      25     // k2
#define HPAD    44     // xT padded (halo 2)
#define CPH     42     // comp padded (halo 1)

typedef unsigned long long u64;

__device__ __forceinline__ u64 dup2f(float x) {
    u64 r; asm("mov.b64 %0,{%1,%1};" : "=l"(r) : "f"(x)); return r;
}
__device__ __forceinline__ void fma2(u64& d, u64 a, u64 b) {
    asm("fma.rn.f32x2 %0,%1,%2,%0;" : "+l"(d) : "l"(a), "l"(b));
}

// ---------------- scratch (zero-initialized at module load; halos stay 0) ----------------
__device__ __align__(16) float  g_xT  [BATCH * HPAD * HPAD * C_IN];  // x NHWC, 2-px zero halo
__device__ __align__(16) float  g_comp[BATCH * CPH  * CPH  * CMID];  // compressed NHWC, halo 1
__device__ __align__(16) float  g_wt  [9 * CMID * CK];               // w_enc [tap][ci][o]
__device__ __align__(16) float  g_wc  [C_IN * CMID];                 // w_comp [c][o]
__device__ __align__(16) float4 g_soft[BATCH * HH * WW * KK];        // softmax wts [b][p][k]{d0..d3}

// ---------------- K0: weight transposes ----------------
__global__ void K0_prep(const float* __restrict__ wcomp,
                        const float* __restrict__ wenc) {
    int i = blockIdx.x * 256 + threadIdx.x;
    if (i < C_IN * CMID) {                    // g_wc[c][o] = wcomp[o][c]
        int c = i >> 6, o = i & 63;
        g_wc[i] = wcomp[o * C_IN + c];
    }
    int j = i - C_IN * CMID;
    if (j >= 0 && j < 9 * CMID * CK) {        // g_wt[tap][ci][o] = wenc[o][ci][tap]
        int tap = j / (CMID * CK);
        int r   = j % (CMID * CK);
        int ci  = r / CK;
        int o   = r % CK;
        g_wt[j] = wenc[o * (CMID * 9) + ci * 9 + tap];
    }
}

// ---------------- K1: A-GEMM (0..199, cp.async depth-2) + x transpose (200..599) ----------------
__global__ void __launch_bounds__(128) K1_compress(const float* __restrict__ x) {
    __shared__ float wbuf[2][4096];   // [c 64][o 64] per chunk
    __shared__ float xbuf[2][1024];   // [c 64][px 16] per chunk

    const int t   = threadIdx.x;
    const int blk = blockIdx.x;

    if (blk < 200) {
        const int g = blk * 16;             // global pixel (incl batch), 16-aligned
        const int b = g / (HH * WW);
        const int p = g % (HH * WW);
        const int px = t & 15;
        const int o0 = (t >> 4) << 3;       // 8 consecutive outputs

        #define A_ISSUE(k) do {                                                     \
            const float4* ws_ = (const float4*)(g_wc + (k) * 4096);                 \
            float4* wd_ = (float4*)wbuf[(k) & 1];                                   \
            _Pragma("unroll")                                                       \
            for (int r_ = 0; r_ < 8; r_++)                                          \
                __pipeline_memcpy_async(&wd_[t + r_ * 128], &ws_[t + r_ * 128], 16);\
            _Pragma("unroll")                                                       \
            for (int r_ = 0; r_ < 2; r_++) {                                        \
                int f_ = t + r_ * 128; int row_ = f_ >> 2, c4_ = f_ & 3;            \
                __pipeline_memcpy_async(&xbuf[(k) & 1][row_ * 16 + c4_ * 4],        \
                    &x[((size_t)(b * C_IN) + (k) * 64 + row_) * (HH * WW) + p + c4_ * 4], 16); \
            }                                                                       \
            __pipeline_commit();                                                    \
        } while (0)

        A_ISSUE(0);
        A_ISSUE(1);

        u64 acc0 = 0, acc1 = 0, acc2 = 0, acc3 = 0;
        for (int k = 0; k < 4; k++) {
            if (k < 3) __pipeline_wait_prior(1); else __pipeline_wait_prior(0);
            __syncthreads();
            const float* w_s = wbuf[k & 1];
            const float* x_s = xbuf[k & 1];
            #pragma unroll 8
            for (int c = 0; c < 64; c++) {
                u64 xx = dup2f(x_s[c * 16 + px]);
                ulonglong2 wA = *(const ulonglong2*)&w_s[c * 64 + o0];
                ulonglong2 wB = *(const ulonglong2*)&w_s[c * 64 + o0 + 4];
                fma2(acc0, xx, wA.x); fma2(acc1, xx, wA.y);
                fma2(acc2, xx, wB.x); fma2(acc3, xx, wB.y);
            }
            __syncthreads();
            if (k + 2 < 4) A_ISSUE(k + 2);
        }
        #undef A_ISSUE

        const int pix = p + px;
        const int hs = pix / WW, ws = pix % WW;
        float* dst = &g_comp[((size_t)(b * CPH + hs + 1) * CPH + (ws + 1)) * CMID + o0];
        *(ulonglong2*)(dst)     = make_ulonglong2(acc0, acc1);
        *(ulonglong2*)(dst + 4) = make_ulonglong2(acc2, acc3);
    } else {
        // ---- x transpose: 32 px x 64 ch tile through smem ----
        float* s = wbuf[0];                 // reuse (needs 64*33 = 2112 <= 4096)
        const int tb = blk - 200;
        const int pg = (tb % 100) * 32;
        const int c0 = (tb / 100) * 64;
        const int b  = pg / (HH * WW);
        const int p0 = pg % (HH * WW);
        #pragma unroll
        for (int r = 0; r < 16; r++) {
            int idx = t + r * 128;
            int cl = idx >> 5, pl = idx & 31;
            s[cl * 33 + pl] = x[((size_t)(b * C_IN) + c0 + cl) * (HH * WW) + p0 + pl];
        }
        __syncthreads();
        #pragma unroll
        for (int r = 0; r < 16; r++) {
            int idx = t + r * 128;
            int pl = idx >> 6, cl = idx & 63;
            int pxg = p0 + pl;
            int hs = pxg / WW, ws = pxg % WW;
            g_xT[((size_t)(b * HPAD + hs + 2) * HPAD + (ws + 2)) * C_IN + c0 + cl] =
                s[cl * 33 + pl];
        }
    }
}

// ---------------- K2: 3x3 encoder conv (all 100 ch) + fused softmax ----------------
// 160 blocks = b(2) x rowpair(20) x colseg(4); 256 threads (250 active in mainloop).
// Thread (og = t/5: o-pair of 100, cp = t%5: 2x2 px). Weights streamed from L2.
#define CS_STRIDE 66

__global__ void __launch_bounds__(256) K2_encoder() {
    __shared__ float  comp_s[48 * CS_STRIDE];   // 12.7 KB
    __shared__ float  kk[20 * CK];              // kern logits [px][100] (8 KB)
    __shared__ float4 ss[20 * KK];              // softmax out [pl][k]{d0..d3} (8 KB)

    const int t    = threadIdx.x;
    const int blk  = blockIdx.x;
    const int b    = blk / 80;
    const int rem  = blk % 80;
    const int r0   = (rem / 4) * 2;             // kern rows r0, r0+1
    const int cs0  = (rem % 4) * 10;            // kern cols cs0..cs0+9

    // comp tile: padded rows r0..r0+3, cols cs0..cs0+11
    #pragma unroll
    for (int r = 0; r < 6; r++) {
        int i  = t + r * 256;
        int px = i >> 5, c2 = i & 31;
        int dr = px / 12, dc = px % 12;
        *(float2*)&comp_s[px * CS_STRIDE + c2 * 2] =
            *(const float2*)&g_comp[((size_t)(b * CPH + r0 + dr) * CPH + cs0 + dc) * CMID + c2 * 2];
    }
    __syncthreads();

    const int og = t / 5;                       // 0..51 (active < 50)
    const int cp = t % 5;

    u64 a00 = 0, a01 = 0, a10 = 0, a11 = 0;
    if (og < 50) {
        const float* wt0 = &g_wt[og * 2];
        #pragma unroll
        for (int tap = 0; tap < 9; tap++) {
            const float* xb = &comp_s[((tap / 3) * 12 + 2 * cp + (tap % 3)) * CS_STRIDE];
            const float* wt = wt0 + tap * (CMID * CK);
            #pragma unroll 8
            for (int ci = 0; ci < CMID; ci += 2) {
                float2 x00 = *(const float2*)&xb[ci];
                float2 x01 = *(const float2*)&xb[CS_STRIDE + ci];
                float2 x10 = *(const float2*)&xb[12 * CS_STRIDE + ci];
                float2 x11 = *(const float2*)&xb[13 * CS_STRIDE + ci];
                u64 w0 = *(const u64*)&wt[ci * CK];
                u64 w1 = *(const u64*)&wt[ci * CK + CK];
                fma2(a00, dup2f(x00.x), w0); fma2(a01, dup2f(x01.x), w0);
                fma2(a10, dup2f(x10.x), w0); fma2(a11, dup2f(x11.x), w0);
                fma2(a00, dup2f(x00.y), w1); fma2(a01, dup2f(x01.y), w1);
                fma2(a10, dup2f(x10.y), w1); fma2(a11, dup2f(x11.y), w1);
            }
        }
    }
    __syncthreads();
    if (og < 50) {                              // stage logits: px = dr*10 + col
        *(u64*)&kk[(2 * cp)      * CK + 2 * og] = a00;
        *(u64*)&kk[(2 * cp + 1)  * CK + 2 * og] = a01;
        *(u64*)&kk[(10 + 2 * cp) * CK + 2 * og] = a10;
        *(u64*)&kk[(11 + 2 * cp) * CK + 2 * og] = a11;
    }
    __syncthreads();

    // ---- 80 softmaxes: (20 kern px) x (sh, sw) ----
    const int wid = t >> 5, lane = t & 31;
    for (int s = wid; s < 80; s += 8) {
        const int px = s >> 2, q = s & 3;
        const int sh = q >> 1, sw = q & 1;
        const int dr = px / 10, wk = cs0 + px % 10;
        float v = -3.0e38f;
        if (lane < KK)
            v = kk[px * CK + lane * 4 + sh * 2 + sw];
        float m = v;
        #pragma unroll
        for (int off = 16; off; off >>= 1)
            m = fmaxf(m, __shfl_xor_sync(0xffffffffu, m, off));
        float e = (lane < KK) ? __expf(v - m) : 0.f;
        float su = e;
        #pragma unroll
        for (int off = 16; off; off >>= 1)
            su += __shfl_xor_sync(0xffffffffu, su, off);
        // source pixel served: p = 20*(2*(r0+dr)+sh) + (wk>>1); subpixel d = 2*(wk&1)+sw
        const int pl = (2 * dr + sh) * 5 + ((wk >> 1) - (cs0 >> 1));
        const int d  = 2 * (wk & 1) + sw;
        if (lane < KK)
            ((float*)&ss[pl * KK + lane])[d] = e / su;
    }
    __syncthreads();

    // ---- store g_soft: 500 f4, coalesced ----
    #pragma unroll
    for (int r = 0; r < 2; r++) {
        int f = t + r * 256;
        if (f < 500) {
            int pl = f / KK, k = f % KK;
            int hu = 2 * r0 + pl / 5;
            int p  = 20 * hu + (cs0 >> 1) + pl % 5;
            g_soft[((size_t)b * (HH * WW) + p) * KK + k] = ss[f];
        }
    }
}

// ---------------- K3: reassembly (pure load-FMA-store) ----------------
// 640 blocks x 256 threads: 5 source px per block, thread = 1 channel.
#define ST_STRIDE 24

__global__ void __launch_bounds__(256) K3_reassemble(float* __restrict__ out) {
    __shared__ float4 sk[5 * KK];           // softmax weights (2 KB)
    __shared__ float  st[256 * ST_STRIDE];  // output staging (24.6 KB)

    const int t   = threadIdx.x;
    const int blk = blockIdx.x;
    const int b   = blk / 320;
    const int p0  = (blk % 320) * 5;

    const int hu    = p0 / 20, pm0 = p0 % 20;
    const int hsrc  = p0 / WW, wsrc0 = p0 % WW;

    if (t < 125)
        sk[t] = g_soft[((size_t)b * (HH * WW) + p0) * KK + t];

    // window loads: 5 rows x 9 cols, all in flight
    const float* xb = &g_xT[((size_t)(b * HPAD + hsrc) * HPAD + wsrc0) * C_IN + t];
    float xw[45];
    #pragma unroll
    for (int r = 0; r < 5; r++)
        #pragma unroll
        for (int c = 0; c < 9; c++)
            xw[r * 9 + c] = xb[(r * HPAD + c) * C_IN];
    __syncthreads();

    #pragma unroll
    for (int i = 0; i < 5; i++) {
        const ulonglong2* skp = (const ulonglong2*)&sk[i * KK];
        u64 a01 = 0, a23 = 0;
        #pragma unroll
        for (int k = 0; k < 25; k++) {
            u64 xx = dup2f(xw[(k / 5) * 9 + i + (k % 5)]);
            ulonglong2 w = skp[k];
            fma2(a01, xx, w.x);
            fma2(a23, xx, w.y);
        }
        *(u64*)&st[t * ST_STRIDE + i * 4]     = a01;
        *(u64*)&st[t * ST_STRIDE + i * 4 + 2] = a23;
    }
    __syncthreads();

    const size_t obase = ((size_t)(b * C_IN) * (2 * HH) + hu) * (2 * WW) + pm0 * 4;
    #pragma unroll
    for (int j = 0; j < 5; j++) {
        int f  = t + j * 256;
        int ch = f / 5, w4 = f % 5;
        float4 v = *(const float4*)&st[ch * ST_STRIDE + w4 * 4];
        *(float4*)&out[obase + (size_t)ch * (4 * HH * WW) + w4 * 4] = v;
    }
}

// ---------------- launch ----------------
extern "C" void kernel_launch(void* const* d_in, const int* in_sizes, int n_in,
                              void* d_out, int out_size) {
    const float* x     = (const float*)d_in[0];
    const float* wcomp = (const float*)d_in[1];
    const float* wenc  = (const float*)d_in[2];
    float* out = (float*)d_out;

    K0_prep<<<(C_IN * CMID + 9 * CMID * CK + 255) / 256, 256>>>(wcomp, wenc);
    K1_compress<<<600, 128>>>(x);
    K2_encoder<<<160, 256>>>();
    K3_reassemble<<<640, 256>>>(out);
}